// round 5
// baseline (speedup 1.0000x reference)
#include <cuda_runtime.h>
#include <math.h>

// DiffJPEG forward: fused kernel, thread-quad per 8x8 block, f32x2-packed math.
// img: (16,3,512,512) f32, quality: int scalar, out: (16,3,512,512) f32.

#define IMG_W 512
#define IMG_H 512
#define BATCH 16
#define NTHREADS 384
#define NUNITS 96                   // 3 ch * 32 blocks per half-strip
#define SMEM_FLOATS (NUNITS * 72)   // 6912 floats = 27648 B (static)

typedef unsigned long long ull;

// ---- f32x2 packed helpers (sm_103a) ----
__device__ __forceinline__ ull pk2(float lo, float hi) {
    ull r; asm("mov.b64 %0, {%1, %2};" : "=l"(r) : "f"(lo), "f"(hi)); return r;
}
__device__ __forceinline__ ull c2(float f) {
    ull r; asm("mov.b64 %0, {%1, %1};" : "=l"(r) : "f"(f)); return r;
}
__device__ __forceinline__ void up2(ull v, float& lo, float& hi) {
    asm("mov.b64 {%0, %1}, %2;" : "=f"(lo), "=f"(hi) : "l"(v));
}
__device__ __forceinline__ ull add2(ull a, ull b) {
    ull r; asm("add.rn.f32x2 %0, %1, %2;" : "=l"(r) : "l"(a), "l"(b)); return r;
}
__device__ __forceinline__ ull sub2(ull a, ull b) {
    ull r; asm("sub.rn.f32x2 %0, %1, %2;" : "=l"(r) : "l"(a), "l"(b)); return r;
}
__device__ __forceinline__ ull mul2(ull a, ull b) {
    ull r; asm("mul.rn.f32x2 %0, %1, %2;" : "=l"(r) : "l"(a), "l"(b)); return r;
}
__device__ __forceinline__ ull fma2(ull a, ull b, ull c) {
    ull r; asm("fma.rn.f32x2 %0, %1, %2, %3;" : "=l"(r) : "l"(a), "l"(b), "l"(c)); return r;
}

// Orthonormal 8-pt DCT-II butterfly constants
#define CAf  0.35355339059327373f
#define CB1f 0.46193976625564337f
#define CB3f 0.19134171618254492f
#define CD1f 0.49039264020161522f
#define CD3f 0.41573480615127262f
#define CD5f 0.27778511650980114f
#define CD7f 0.09754516100806413f
#define MAGICf 12582912.0f          // 1.5*2^23 round-to-even

// Packed forward DCT-II (y = M @ x), operates on 8 ull lvalues.
#define FDCT8P(x0,x1,x2,x3,x4,x5,x6,x7) do {                                  \
    ull e0=add2(x0,x7), e1=add2(x1,x6), e2=add2(x2,x5), e3=add2(x3,x4);       \
    ull o0=sub2(x0,x7), o1=sub2(x1,x6), o2=sub2(x2,x5), o3=sub2(x3,x4);       \
    ull ee0=add2(e0,e3), ee1=add2(e1,e2), eo0=sub2(e0,e3), eo1=sub2(e1,e2);   \
    x0 = mul2(add2(ee0,ee1), KCA);                                            \
    x4 = mul2(sub2(ee0,ee1), KCA);                                            \
    x2 = fma2(eo0, KB1, mul2(eo1, KB3));                                      \
    x6 = sub2(mul2(eo0, KB3), mul2(eo1, KB1));                                \
    { ull t = mul2(o0,KD1); t = fma2(o1,KD3,t); t = fma2(o2,KD5,t);           \
      x1 = fma2(o3,KD7,t); }                                                  \
    { ull t = mul2(o1,KD7); t = fma2(o2,KD1,t); t = fma2(o3,KD5,t);           \
      x3 = sub2(mul2(o0,KD3), t); }                                           \
    { ull t = mul2(o0,KD5); t = fma2(o2,KD7,t); t = fma2(o3,KD3,t);           \
      x5 = sub2(t, mul2(o1,KD1)); }                                           \
    { ull t  = sub2(mul2(o0,KD7), mul2(o1,KD5));                              \
      ull t2 = sub2(mul2(o2,KD3), mul2(o3,KD1));                              \
      x7 = add2(t, t2); }                                                     \
} while(0)

// Packed inverse (DCT-III, x = M^T @ y)
#define IDCT8P(x0,x1,x2,x3,x4,x5,x6,x7) do {                                  \
    ull ee0 = mul2(add2(x0,x4), KCA), ee1 = mul2(sub2(x0,x4), KCA);           \
    ull eo0 = fma2(x2, KB1, mul2(x6, KB3));                                   \
    ull eo1 = sub2(mul2(x2, KB3), mul2(x6, KB1));                             \
    ull o0, o1, o2, o3;                                                       \
    { ull t = mul2(x1,KD1); t = fma2(x3,KD3,t); t = fma2(x5,KD5,t);           \
      o0 = fma2(x7,KD7,t); }                                                  \
    { ull t = mul2(x3,KD7); t = fma2(x5,KD1,t); t = fma2(x7,KD5,t);           \
      o1 = sub2(mul2(x1,KD3), t); }                                           \
    { ull t = mul2(x1,KD5); t = fma2(x5,KD7,t); t = fma2(x7,KD3,t);           \
      o2 = sub2(t, mul2(x3,KD1)); }                                           \
    { ull t  = sub2(mul2(x1,KD7), mul2(x3,KD5));                              \
      ull t2 = sub2(mul2(x5,KD3), mul2(x7,KD1));                              \
      o3 = add2(t, t2); }                                                     \
    ull e0=add2(ee0,eo0), e3=sub2(ee0,eo0), e1=add2(ee1,eo1), e2=sub2(ee1,eo1);\
    x0=add2(e0,o0); x7=sub2(e0,o0); x1=add2(e1,o1); x6=sub2(e1,o1);           \
    x2=add2(e2,o2); x5=sub2(e2,o2); x3=add2(e3,o3); x4=sub2(e3,o3);           \
} while(0)

__constant__ float c_lum[64] = {
    16, 11, 10, 16, 24, 40, 51, 61,
    12, 12, 14, 19, 26, 58, 60, 55,
    14, 13, 16, 24, 40, 57, 69, 56,
    14, 17, 22, 29, 51, 87, 80, 62,
    18, 22, 37, 56, 68, 109, 103, 77,
    24, 35, 55, 64, 81, 104, 113, 92,
    49, 64, 78, 87, 103, 121, 120, 101,
    72, 92, 95, 98, 112, 100, 103, 99
};
__constant__ float c_chrom[64] = {
    17, 18, 24, 47, 99, 99, 99, 99,
    18, 21, 26, 66, 99, 99, 99, 99,
    24, 26, 56, 99, 99, 99, 99, 99,
    47, 66, 99, 99, 99, 99, 99, 99,
    99, 99, 99, 99, 99, 99, 99, 99,
    99, 99, 99, 99, 99, 99, 99, 99,
    99, 99, 99, 99, 99, 99, 99, 99,
    99, 99, 99, 99, 99, 99, 99, 99
};

__global__ void __launch_bounds__(NTHREADS, 2)
jpeg_kernel(const float* __restrict__ img,
            const int* __restrict__ quality,
            float* __restrict__ out)
{
    __shared__ float sm[SMEM_FLOATS];            // 96 units * 72 floats
    __shared__ __align__(8) float qv[64], qr[64]; // per-l-pair packed q / 1/q
    __shared__ __align__(8) float qv2[64], qr2[64];

    const int tid = threadIdx.x;

    if (tid < 128) {
        int i = tid & 63;
        int q = *quality;
        q = max(1, min(100, q));
        float scale = (q < 50) ? (5000.0f / (float)q) : (200.0f - 2.0f * (float)q);
        float base = (tid < 64) ? c_lum[i] : c_chrom[i];
        float v = (base * scale + 50.0f) / 100.0f;
        v = fminf(fmaxf(v, 1.0f), 255.0f);
        if (tid < 64) { qv[i] = v; qr[i] = 1.0f / v; }
        else          { qv2[i] = v; qr2[i] = 1.0f / v; }
    }

    const int bid = blockIdx.x;
    const int b = bid >> 7;              // batch
    const int r7 = bid & 127;
    const int strip = r7 >> 1;           // 8-row strip
    const int halfc = r7 & 1;            // column half
    const int row0 = strip * 8;
    const int col0 = halfc << 8;         // 0 or 256
    const size_t CH = (size_t)IMG_H * IMG_W;
    const size_t img_base = (size_t)b * 3 * CH;

    // ---- Phase A: load + RGB->YCbCr (x255 folded) into block-slot smem ----
    #pragma unroll
    for (int g = 0; g < 2; g++) {
        int idx = tid + g * NTHREADS;
        if (idx < 512) {
            int r = idx >> 6;                 // 0..7
            int cg = idx & 63;                // float4 group within half-strip
            int col = col0 + (cg << 2);
            size_t off = img_base + (size_t)(row0 + r) * IMG_W + col;
            float4 r4 = *(const float4*)(img + off);
            float4 g4 = *(const float4*)(img + off + CH);
            float4 b4 = *(const float4*)(img + off + 2 * CH);
            float4 y4, cb4, cr4;
            {
                const float* Rp = &r4.x; const float* Gp = &g4.x; const float* Bp = &b4.x;
                float* Yp = &y4.x; float* Cbp = &cb4.x; float* Crp = &cr4.x;
                #pragma unroll
                for (int j = 0; j < 4; j++) {
                    float R = Rp[j], G = Gp[j], B = Bp[j];
                    Yp[j]  = fmaf(76.245f, R, fmaf(149.685f, G, 29.07f * B));
                    Cbp[j] = fmaf(-43.0185f, R, fmaf(-84.4815f, G, fmaf(127.5f, B, 128.0f)));
                    Crp[j] = fmaf(127.5f, R, fmaf(-106.7685f, G, fmaf(-20.7315f, B, 128.0f)));
                }
            }
            int blk = cg >> 1;                // local block 0..31
            int sb = blk * 72 + (r >> 2) * 36 + (r & 3) * 8 + ((cg & 1) << 2);
            *(float4*)(sm + sb)            = y4;
            *(float4*)(sm + 32 * 72 + sb)  = cb4;
            *(float4*)(sm + 64 * 72 + sb)  = cr4;
        }
    }
    __syncthreads();

    // ---- Phase B: thread quad per 8x8 block, f32x2-packed math ----
    {
        const ull KCA = c2(CAf), KB1 = c2(CB1f), KB3 = c2(CB3f);
        const ull KD1 = c2(CD1f), KD3 = c2(CD3f), KD5 = c2(CD5f), KD7 = c2(CD7f);
        const ull KMAG = c2(MAGICf);

        const int unit = tid >> 2;        // 0..95 = c*32 + blk
        const int q = tid & 3;            // row-pair index
        const int c = unit >> 5;
        float* ub = sm + unit * 72;

        // --- load rows 2q, 2q+1 (row-major), pack per-column pairs ---
        ull X0,X1,X2,X3,X4,X5,X6,X7;
        {
            int a0 = 2 * q, a1 = 2 * q + 1;
            float* p0 = ub + (a0 >> 2) * 36 + (a0 & 3) * 8;
            float* p1 = ub + (a1 >> 2) * 36 + (a1 & 3) * 8;
            float4 u0 = *(const float4*)(p0), u1 = *(const float4*)(p0 + 4);
            float4 v0 = *(const float4*)(p1), v1 = *(const float4*)(p1 + 4);
            X0 = pk2(u0.x, v0.x); X1 = pk2(u0.y, v0.y);
            X2 = pk2(u0.z, v0.z); X3 = pk2(u0.w, v0.w);
            X4 = pk2(u1.x, v1.x); X5 = pk2(u1.y, v1.y);
            X6 = pk2(u1.z, v1.z); X7 = pk2(u1.w, v1.w);
        }
        // row forward DCT (both rows at once)
        FDCT8P(X0,X1,X2,X3,X4,X5,X6,X7);

        __syncwarp();
        // transpose store T1: X[l] is exactly pair (r=2q, 2q+1) -> STS.64
        {
            ull* t;
            t = (ull*)(ub + 0*36 + 0*8 + 2*q); t[0] = X0;
            t = (ull*)(ub + 0*36 + 1*8 + 2*q); t[0] = X1;
            t = (ull*)(ub + 0*36 + 2*8 + 2*q); t[0] = X2;
            t = (ull*)(ub + 0*36 + 3*8 + 2*q); t[0] = X3;
            t = (ull*)(ub + 1*36 + 0*8 + 2*q); t[0] = X4;
            t = (ull*)(ub + 1*36 + 1*8 + 2*q); t[0] = X5;
            t = (ull*)(ub + 1*36 + 2*8 + 2*q); t[0] = X6;
            t = (ull*)(ub + 1*36 + 3*8 + 2*q); t[0] = X7;
        }
        __syncwarp();

        // --- load T1 rows l=2q, 2q+1 (over r), pack per-r pairs ---
        ull Y0,Y1,Y2,Y3,Y4,Y5,Y6,Y7;
        {
            int a0 = 2 * q, a1 = 2 * q + 1;
            float* p0 = ub + (a0 >> 2) * 36 + (a0 & 3) * 8;
            float* p1 = ub + (a1 >> 2) * 36 + (a1 & 3) * 8;
            float4 u0 = *(const float4*)(p0), u1 = *(const float4*)(p0 + 4);
            float4 v0 = *(const float4*)(p1), v1 = *(const float4*)(p1 + 4);
            Y0 = pk2(u0.x, v0.x); Y1 = pk2(u0.y, v0.y);
            Y2 = pk2(u0.z, v0.z); Y3 = pk2(u0.w, v0.w);
            Y4 = pk2(u1.x, v1.x); Y5 = pk2(u1.y, v1.y);
            Y6 = pk2(u1.z, v1.z); Y7 = pk2(u1.w, v1.w);
        }
        // column forward DCT -> Y[k] holds D[k][l] for l = 2q, 2q+1
        FDCT8P(Y0,Y1,Y2,Y3,Y4,Y5,Y6,Y7);

        // -128 input shift commutes to DC only (lo lane of q==0, k=0)
        if (q == 0) Y0 = sub2(Y0, pk2(1024.0f, 0.0f));

        // quantize: packed q / 1/q pairs over (l=2q, 2q+1); FFMA2 magic round
        {
            const float* QV = ((b * 3 + c) < BATCH) ? qv : qv2;
            const float* QR = ((b * 3 + c) < BATCH) ? qr : qr2;
            int o = 2 * q;
            #define QSTEP(Yk, k) do {                                         \
                ull qq = *(const ull*)(QV + (k)*8 + o);                       \
                ull rr = *(const ull*)(QR + (k)*8 + o);                       \
                ull t = fma2(Yk, rr, KMAG);                                   \
                t = sub2(t, KMAG);                                            \
                Yk = mul2(t, qq);                                             \
            } while(0)
            QSTEP(Y0,0); QSTEP(Y1,1); QSTEP(Y2,2); QSTEP(Y3,3);
            QSTEP(Y4,4); QSTEP(Y5,5); QSTEP(Y6,6); QSTEP(Y7,7);
            #undef QSTEP
        }

        if (q == 0) Y0 = add2(Y0, pk2(1024.0f, 0.0f));

        // column inverse DCT -> Y[i] = T2[i][l] for l = 2q, 2q+1
        IDCT8P(Y0,Y1,Y2,Y3,Y4,Y5,Y6,Y7);

        __syncwarp();
        // transpose store T2: Y[i] is pair over l -> STS.64 at row i, col 2q
        {
            ull* t;
            t = (ull*)(ub + 0*36 + 0*8 + 2*q); t[0] = Y0;
            t = (ull*)(ub + 0*36 + 1*8 + 2*q); t[0] = Y1;
            t = (ull*)(ub + 0*36 + 2*8 + 2*q); t[0] = Y2;
            t = (ull*)(ub + 0*36 + 3*8 + 2*q); t[0] = Y3;
            t = (ull*)(ub + 1*36 + 0*8 + 2*q); t[0] = Y4;
            t = (ull*)(ub + 1*36 + 1*8 + 2*q); t[0] = Y5;
            t = (ull*)(ub + 1*36 + 2*8 + 2*q); t[0] = Y6;
            t = (ull*)(ub + 1*36 + 3*8 + 2*q); t[0] = Y7;
        }
        __syncwarp();

        // --- load T2 rows 2q, 2q+1, pack pairs over rows, row inverse DCT ---
        ull Z0,Z1,Z2,Z3,Z4,Z5,Z6,Z7;
        {
            int a0 = 2 * q, a1 = 2 * q + 1;
            float* p0 = ub + (a0 >> 2) * 36 + (a0 & 3) * 8;
            float* p1 = ub + (a1 >> 2) * 36 + (a1 & 3) * 8;
            float4 u0 = *(const float4*)(p0), u1 = *(const float4*)(p0 + 4);
            float4 v0 = *(const float4*)(p1), v1 = *(const float4*)(p1 + 4);
            Z0 = pk2(u0.x, v0.x); Z1 = pk2(u0.y, v0.y);
            Z2 = pk2(u0.z, v0.z); Z3 = pk2(u0.w, v0.w);
            Z4 = pk2(u1.x, v1.x); Z5 = pk2(u1.y, v1.y);
            Z6 = pk2(u1.z, v1.z); Z7 = pk2(u1.w, v1.w);
        }
        IDCT8P(Z0,Z1,Z2,Z3,Z4,Z5,Z6,Z7);

        // unpack into two spatial rows, store row-major (own rows only)
        {
            float a[8], bb[8];
            up2(Z0, a[0], bb[0]); up2(Z1, a[1], bb[1]);
            up2(Z2, a[2], bb[2]); up2(Z3, a[3], bb[3]);
            up2(Z4, a[4], bb[4]); up2(Z5, a[5], bb[5]);
            up2(Z6, a[6], bb[6]); up2(Z7, a[7], bb[7]);
            int a0 = 2 * q, a1 = 2 * q + 1;
            float* p0 = ub + (a0 >> 2) * 36 + (a0 & 3) * 8;
            float* p1 = ub + (a1 >> 2) * 36 + (a1 & 3) * 8;
            *(float4*)(p0)     = make_float4(a[0], a[1], a[2], a[3]);
            *(float4*)(p0 + 4) = make_float4(a[4], a[5], a[6], a[7]);
            *(float4*)(p1)     = make_float4(bb[0], bb[1], bb[2], bb[3]);
            *(float4*)(p1 + 4) = make_float4(bb[4], bb[5], bb[6], bb[7]);
        }
    }
    __syncthreads();

    // ---- Phase C: YCbCr->RGB, clip, store ----
    #pragma unroll
    for (int g = 0; g < 2; g++) {
        int idx = tid + g * NTHREADS;
        if (idx < 512) {
            int r = idx >> 6;
            int cg = idx & 63;
            int col = col0 + (cg << 2);
            int blk = cg >> 1;
            int sb = blk * 72 + (r >> 2) * 36 + (r & 3) * 8 + ((cg & 1) << 2);
            float4 y4  = *(const float4*)(sm + sb);
            float4 cb4 = *(const float4*)(sm + 32 * 72 + sb);
            float4 cr4 = *(const float4*)(sm + 64 * 72 + sb);
            float4 ro, go, bo;
            {
                const float* Yp = &y4.x; const float* Cbp = &cb4.x; const float* Crp = &cr4.x;
                float* Rp = &ro.x; float* Gp = &go.x; float* Bp = &bo.x;
                #pragma unroll
                for (int j = 0; j < 4; j++) {
                    float y  = Yp[j];
                    float cb = Cbp[j] - 128.0f;
                    float cr = Crp[j] - 128.0f;
                    float rr = y + 1.402f * cr;
                    float gg = y - 0.34414f * cb - 0.71414f * cr;
                    float bb = y + 1.772f * cb;
                    Rp[j] = fminf(fmaxf(rr * (1.0f / 255.0f), 0.0f), 1.0f);
                    Gp[j] = fminf(fmaxf(gg * (1.0f / 255.0f), 0.0f), 1.0f);
                    Bp[j] = fminf(fmaxf(bb * (1.0f / 255.0f), 0.0f), 1.0f);
                }
            }
            size_t off = img_base + (size_t)(row0 + r) * IMG_W + col;
            *(float4*)(out + off)          = ro;
            *(float4*)(out + off + CH)     = go;
            *(float4*)(out + off + 2 * CH) = bo;
        }
    }
}

extern "C" void kernel_launch(void* const* d_in, const int* in_sizes, int n_in,
                              void* d_out, int out_size)
{
    const float* img = (const float*)d_in[0];
    const int* quality = (const int*)d_in[1];
    float* out = (float*)d_out;

    dim3 grid(BATCH * 64 * 2);   // 2048 CTAs: (batch, strip, column half)
    jpeg_kernel<<<grid, NTHREADS>>>(img, quality, out);
}